// round 1
// baseline (speedup 1.0000x reference)
#include <cuda_runtime.h>
#include <math.h>

#define B_  4
#define T_  2048
#define C_  1024
#define NH_ 16
#define HD_ 64
#define M_  (B_*T_)          // 8192 tokens

// Scratch (static device globals: allowed; no runtime allocation)
__device__ float g_qkv[(size_t)M_ * 3 * C_];   // [8192, 3072]
__device__ float g_y  [(size_t)M_ * C_];       // [8192, 1024]  (b,t,h,d)

// ---------------------------------------------------------------------------
// GEMM + bias: C[M,N] = A[M,K] @ B[K,N] + bias[N]
// 64x64 tile, BK=16, 256 threads, 4x4 register tile per thread.
// ---------------------------------------------------------------------------
__global__ __launch_bounds__(256)
void gemm_bias_kernel(const float* __restrict__ A, const float* __restrict__ B,
                      const float* __restrict__ bias, float* __restrict__ C,
                      int M, int N, int K)
{
    __shared__ float As[16][64];   // transposed: As[k][m]
    __shared__ float Bs[16][64];   // Bs[k][n]

    const int tid = threadIdx.x;
    const int tx  = tid & 15;
    const int ty  = tid >> 4;
    const int row0 = blockIdx.y * 64;
    const int col0 = blockIdx.x * 64;

    // A-load mapping: thread -> (row am, 4 consecutive k at ak)
    const int am = tid >> 2;
    const int ak = (tid & 3) << 2;
    // B-load mapping: thread -> (k row bk, 4 consecutive n at bn)
    const int bk = tid >> 4;
    const int bn = (tid & 15) << 2;

    const float* Ag = A + (size_t)(row0 + am) * K + ak;
    const float* Bg = B + (size_t)bk * N + col0 + bn;

    float acc[4][4];
    #pragma unroll
    for (int i = 0; i < 4; i++)
        #pragma unroll
        for (int j = 0; j < 4; j++) acc[i][j] = 0.f;

    for (int k0 = 0; k0 < K; k0 += 16) {
        float4 av = *(const float4*)(Ag + k0);
        As[ak+0][am] = av.x; As[ak+1][am] = av.y;
        As[ak+2][am] = av.z; As[ak+3][am] = av.w;
        *(float4*)&Bs[bk][bn] = *(const float4*)(Bg + (size_t)k0 * N);
        __syncthreads();

        #pragma unroll
        for (int kk = 0; kk < 16; kk++) {
            float4 a = *(const float4*)&As[kk][ty << 2];
            float4 b = *(const float4*)&Bs[kk][tx << 2];
            float ar[4] = {a.x, a.y, a.z, a.w};
            float br[4] = {b.x, b.y, b.z, b.w};
            #pragma unroll
            for (int i = 0; i < 4; i++)
                #pragma unroll
                for (int j = 0; j < 4; j++)
                    acc[i][j] += ar[i] * br[j];
        }
        __syncthreads();
    }

    float4 bv = *(const float4*)(bias + col0 + (tx << 2));
    #pragma unroll
    for (int i = 0; i < 4; i++) {
        float4 o;
        o.x = acc[i][0] + bv.x;
        o.y = acc[i][1] + bv.y;
        o.z = acc[i][2] + bv.z;
        o.w = acc[i][3] + bv.w;
        *(float4*)(C + (size_t)(row0 + (ty << 2) + i) * N + col0 + (tx << 2)) = o;
    }
}

// ---------------------------------------------------------------------------
// Flash attention (causal), fp32. One CTA per (q-block of 64, head, batch).
// BQ = BK = 64, HD = 64, 256 threads, online softmax, O in registers (4x4).
// Dynamic SMEM: Qt[64][64] + KV[64][64] + Ss[64][65] + m/l/alpha[64 each]
// ---------------------------------------------------------------------------
__global__ __launch_bounds__(256)
void attn_kernel(const float* __restrict__ qkv, float* __restrict__ y)
{
    extern __shared__ float sm[];
    float* Qt   = sm;                 // [64][64], d-major: Qt[d*64 + m]
    float* KV   = Qt + 64 * 64;       // K: Kt[d*64 + n]; later V: Vs[key*64 + d]
    float* Ss   = KV + 64 * 64;       // [64][65]
    float* mrow = Ss + 64 * 65;       // [64]
    float* lrow = mrow + 64;          // [64]
    float* arow = lrow + 64;          // [64]

    const int qb = (gridDim.x - 1) - blockIdx.x;  // heavy blocks first
    const int h  = blockIdx.y;
    const int b  = blockIdx.z;
    const int tid = threadIdx.x;
    const int tx  = tid & 15;
    const int ty  = tid >> 4;

    const float scale = 0.125f;  // 1/sqrt(64)

    // load mapping for 64x64 fp32 tiles: thread -> (row am, 16 d at ak16)
    const int am   = tid >> 2;
    const int ak16 = (tid & 3) << 4;

    // ---- load Q (transposed to d-major) ----
    {
        const float* qbase = qkv + (size_t)(b * T_ + qb * 64 + am) * (3 * C_)
                                 + h * HD_ + ak16;
        #pragma unroll
        for (int i = 0; i < 4; i++) {
            float4 v = *(const float4*)(qbase + i * 4);
            int d = ak16 + i * 4;
            Qt[(d+0)*64 + am] = v.x; Qt[(d+1)*64 + am] = v.y;
            Qt[(d+2)*64 + am] = v.z; Qt[(d+3)*64 + am] = v.w;
        }
    }
    if (tid < 64) { mrow[tid] = -1e30f; lrow[tid] = 0.f; }

    float o[4][4];
    #pragma unroll
    for (int i = 0; i < 4; i++)
        #pragma unroll
        for (int j = 0; j < 4; j++) o[i][j] = 0.f;

    for (int kb = 0; kb <= qb; kb++) {
        __syncthreads();   // prev PV done (and Q load on first iter)

        // ---- load K tile transposed into KV ----
        {
            const float* kbase = qkv + (size_t)(b * T_ + kb * 64 + am) * (3 * C_)
                                     + C_ + h * HD_ + ak16;
            #pragma unroll
            for (int i = 0; i < 4; i++) {
                float4 v = *(const float4*)(kbase + i * 4);
                int d = ak16 + i * 4;
                KV[(d+0)*64 + am] = v.x; KV[(d+1)*64 + am] = v.y;
                KV[(d+2)*64 + am] = v.z; KV[(d+3)*64 + am] = v.w;
            }
        }
        __syncthreads();

        // ---- S = Q K^T  (4x4 per thread) ----
        float s[4][4];
        #pragma unroll
        for (int i = 0; i < 4; i++)
            #pragma unroll
            for (int j = 0; j < 4; j++) s[i][j] = 0.f;

        #pragma unroll 8
        for (int kk = 0; kk < 64; kk++) {
            float4 a = *(const float4*)&Qt[kk * 64 + (ty << 2)];
            float4 bb = *(const float4*)&KV[kk * 64 + (tx << 2)];
            float ar[4] = {a.x, a.y, a.z, a.w};
            float br[4] = {bb.x, bb.y, bb.z, bb.w};
            #pragma unroll
            for (int i = 0; i < 4; i++)
                #pragma unroll
                for (int j = 0; j < 4; j++)
                    s[i][j] += ar[i] * br[j];
        }

        // scale + causal mask, write to Ss
        #pragma unroll
        for (int i = 0; i < 4; i++) {
            int qrow = qb * 64 + (ty << 2) + i;
            #pragma unroll
            for (int j = 0; j < 4; j++) {
                int kcol = kb * 64 + (tx << 2) + j;
                float val = (kcol > qrow) ? -1e30f : s[i][j] * scale;
                Ss[((ty << 2) + i) * 65 + (tx << 2) + j] = val;
            }
        }
        __syncthreads();

        // ---- load V tile (row-major, overwrites K) ----
        {
            const float* vbase = qkv + (size_t)(b * T_ + kb * 64 + am) * (3 * C_)
                                     + 2 * C_ + h * HD_ + ak16;
            #pragma unroll
            for (int i = 0; i < 4; i++)
                *(float4*)&KV[am * 64 + ak16 + i * 4] =
                    *(const float4*)(vbase + i * 4);
        }

        // ---- online softmax: 4 threads per row, 16 cols each ----
        {
            const int row = tid >> 2;
            const int seg = (tid & 3) << 4;
            float mx = -1e30f;
            #pragma unroll
            for (int c = 0; c < 16; c++)
                mx = fmaxf(mx, Ss[row * 65 + seg + c]);
            mx = fmaxf(mx, __shfl_xor_sync(0xffffffffu, mx, 1));
            mx = fmaxf(mx, __shfl_xor_sync(0xffffffffu, mx, 2));
            float mold = mrow[row];
            float mnew = fmaxf(mold, mx);
            float sum = 0.f;
            #pragma unroll
            for (int c = 0; c < 16; c++) {
                float p = __expf(Ss[row * 65 + seg + c] - mnew);
                Ss[row * 65 + seg + c] = p;
                sum += p;
            }
            sum += __shfl_xor_sync(0xffffffffu, sum, 1);
            sum += __shfl_xor_sync(0xffffffffu, sum, 2);
            if ((tid & 3) == 0) {
                float alpha = __expf(mold - mnew);
                arow[row] = alpha;
                lrow[row] = lrow[row] * alpha + sum;
                mrow[row] = mnew;
            }
        }
        __syncthreads();

        // ---- O = O*alpha + P @ V ----
        float al[4];
        #pragma unroll
        for (int i = 0; i < 4; i++) al[i] = arow[(ty << 2) + i];
        #pragma unroll
        for (int i = 0; i < 4; i++)
            #pragma unroll
            for (int j = 0; j < 4; j++) o[i][j] *= al[i];

        #pragma unroll 8
        for (int kk = 0; kk < 64; kk++) {
            float p[4];
            #pragma unroll
            for (int i = 0; i < 4; i++)
                p[i] = Ss[((ty << 2) + i) * 65 + kk];
            float4 vv = *(const float4*)&KV[kk * 64 + (tx << 2)];
            float vr[4] = {vv.x, vv.y, vv.z, vv.w};
            #pragma unroll
            for (int i = 0; i < 4; i++)
                #pragma unroll
                for (int j = 0; j < 4; j++)
                    o[i][j] += p[i] * vr[j];
        }
    }

    // ---- epilogue: divide by l, write y[b, q, h, d] ----
    #pragma unroll
    for (int i = 0; i < 4; i++) {
        float linv = 1.f / lrow[(ty << 2) + i];
        float4 ov;
        ov.x = o[i][0] * linv; ov.y = o[i][1] * linv;
        ov.z = o[i][2] * linv; ov.w = o[i][3] * linv;
        int q = qb * 64 + (ty << 2) + i;
        *(float4*)(y + (size_t)(b * T_ + q) * C_ + h * HD_ + (tx << 2)) = ov;
    }
}

// ---------------------------------------------------------------------------
extern "C" void kernel_launch(void* const* d_in, const int* in_sizes, int n_in,
                              void* d_out, int out_size)
{
    const float* x      = (const float*)d_in[0];
    const float* W_attn = (const float*)d_in[1];
    const float* b_attn = (const float*)d_in[2];
    const float* W_proj = (const float*)d_in[3];
    const float* b_proj = (const float*)d_in[4];
    float* out = (float*)d_out;

    float *qkv_ptr, *y_ptr;
    cudaGetSymbolAddress((void**)&qkv_ptr, g_qkv);
    cudaGetSymbolAddress((void**)&y_ptr,   g_y);

    const int ATTN_SMEM = (64*64 + 64*64 + 64*65 + 3*64) * (int)sizeof(float);
    cudaFuncSetAttribute(attn_kernel,
                         cudaFuncAttributeMaxDynamicSharedMemorySize, ATTN_SMEM);

    // 1) qkv = x @ W_attn + b_attn   [8192, 3072]
    {
        dim3 grid(3 * C_ / 64, M_ / 64);
        gemm_bias_kernel<<<grid, 256>>>(x, W_attn, b_attn, qkv_ptr,
                                        M_, 3 * C_, C_);
    }

    // 2) flash attention -> y [8192, 1024]
    {
        dim3 grid(T_ / 64, NH_, B_);
        attn_kernel<<<grid, 256, ATTN_SMEM>>>(qkv_ptr, y_ptr);
    }

    // 3) out = y @ W_proj + b_proj   [8192, 1024]
    {
        dim3 grid(C_ / 64, M_ / 64);
        gemm_bias_kernel<<<grid, 256>>>(y_ptr, W_proj, b_proj, out,
                                        M_, C_, C_);
    }
}

// round 3
// speedup vs baseline: 2.5346x; 2.5346x over previous
#include <cuda_runtime.h>
#include <cuda_bf16.h>
#include <cstdint>
#include <math.h>

#define B_  4
#define T_  2048
#define C_  1024
#define NH_ 16
#define HD_ 64
#define M_  (B_*T_)          // 8192 tokens

// ---------------- scratch (static device globals; no runtime alloc) --------
__device__ __align__(256) float          g_qkv [(size_t)M_ * 3 * C_];
__device__ __align__(256) float          g_y   [(size_t)M_ * C_];
__device__ __align__(256) __nv_bfloat16  g_xhi [(size_t)M_ * C_];
__device__ __align__(256) __nv_bfloat16  g_xlo [(size_t)M_ * C_];
__device__ __align__(256) __nv_bfloat16  g_wthi[(size_t)3 * C_ * C_];  // W_attn^T [3C, C]
__device__ __align__(256) __nv_bfloat16  g_wtlo[(size_t)3 * C_ * C_];
__device__ __align__(256) __nv_bfloat16  g_wpthi[(size_t)C_ * C_];     // W_proj^T [C, C]
__device__ __align__(256) __nv_bfloat16  g_wptlo[(size_t)C_ * C_];
__device__ __align__(256) __nv_bfloat16  g_yhi [(size_t)M_ * C_];
__device__ __align__(256) __nv_bfloat16  g_ylo [(size_t)M_ * C_];

// ---------------- helpers ---------------------------------------------------
__device__ __forceinline__ uint32_t smem_u32(const void* p) {
    uint32_t a;
    asm("{ .reg .u64 t; cvta.to.shared.u64 t, %1; cvt.u32.u64 %0, t; }" : "=r"(a) : "l"(p));
    return a;
}

#define LDSM_X4(r0, r1, r2, r3, addr) \
    asm volatile("ldmatrix.sync.aligned.m8n8.x4.shared.b16 {%0,%1,%2,%3}, [%4];" \
        : "=r"(r0), "=r"(r1), "=r"(r2), "=r"(r3) : "r"(addr))

__device__ __forceinline__ void mma16816(float* d, const uint32_t* a,
                                         uint32_t b0, uint32_t b1) {
    asm volatile(
        "mma.sync.aligned.m16n8k16.row.col.f32.bf16.bf16.f32 "
        "{%0,%1,%2,%3}, {%4,%5,%6,%7}, {%8,%9}, {%0,%1,%2,%3};"
        : "+f"(d[0]), "+f"(d[1]), "+f"(d[2]), "+f"(d[3])
        : "r"(a[0]), "r"(a[1]), "r"(a[2]), "r"(a[3]), "r"(b0), "r"(b1));
}

// ---------------- conversion kernels ----------------------------------------
__global__ __launch_bounds__(256)
void convert_hilo(const float* __restrict__ in, __nv_bfloat16* __restrict__ hi,
                  __nv_bfloat16* __restrict__ lo, int n)
{
    int i = (blockIdx.x * 256 + threadIdx.x) * 4;
    if (i >= n) return;
    float4 v = *(const float4*)(in + i);
    __nv_bfloat16 h0 = __float2bfloat16_rn(v.x);
    __nv_bfloat16 h1 = __float2bfloat16_rn(v.y);
    __nv_bfloat16 h2 = __float2bfloat16_rn(v.z);
    __nv_bfloat16 h3 = __float2bfloat16_rn(v.w);
    __nv_bfloat16 hv[4] = {h0, h1, h2, h3};
    __nv_bfloat16 lv[4] = {
        __float2bfloat16_rn(v.x - __bfloat162float(h0)),
        __float2bfloat16_rn(v.y - __bfloat162float(h1)),
        __float2bfloat16_rn(v.z - __bfloat162float(h2)),
        __float2bfloat16_rn(v.w - __bfloat162float(h3))};
    *(uint2*)(hi + i) = *(uint2*)hv;
    *(uint2*)(lo + i) = *(uint2*)lv;
}

// W [K,N] fp32 -> Wt hi/lo [N,K] bf16 (transpose + split)
__global__ __launch_bounds__(256)
void transpose_convert(const float* __restrict__ W, __nv_bfloat16* __restrict__ Thi,
                       __nv_bfloat16* __restrict__ Tlo, int K, int N)
{
    __shared__ float t[32][33];
    int n0 = blockIdx.x * 32, k0 = blockIdx.y * 32;
    int tx = threadIdx.x & 31, ty = threadIdx.x >> 5;  // 32x8
    #pragma unroll
    for (int i = 0; i < 32; i += 8)
        t[ty + i][tx] = W[(size_t)(k0 + ty + i) * N + n0 + tx];
    __syncthreads();
    #pragma unroll
    for (int i = 0; i < 32; i += 8) {
        float v = t[tx][ty + i];
        size_t o = (size_t)(n0 + ty + i) * K + k0 + tx;
        __nv_bfloat16 h = __float2bfloat16_rn(v);
        Thi[o] = h;
        Tlo[o] = __float2bfloat16_rn(v - __bfloat162float(h));
    }
}

// ---------------- mma.sync GEMM: C[M,N] = A[M,K] @ B[N,K]^T + bias ----------
// 128x128 CTA tile, 8 warps (4m x 2n), warp tile 32x64, k-chunk 32.
// bf16 hi/lo split: acc += Ahi*Bhi + Ahi*Blo + Alo*Bhi (fp32 accum).
// SMEM rows: 64B data padded to 80B stride (16B aligned, conflict-free ldmatrix).
#define ASTR 80
#define SM_AHI 0
#define SM_ALO 10240
#define SM_BHI 20480
#define SM_BLO 30720
#define SM_BIAS 40960

__global__ __launch_bounds__(256)
void gemm_mma_kernel(const __nv_bfloat16* __restrict__ Ahi, const __nv_bfloat16* __restrict__ Alo,
                     const __nv_bfloat16* __restrict__ Bhi, const __nv_bfloat16* __restrict__ Blo,
                     const float* __restrict__ bias, float* __restrict__ Cout,
                     int M, int N, int K)
{
    __shared__ __align__(16) char sm[41472];
    float* sbias = (float*)(sm + SM_BIAS);
    const uint32_t smb = smem_u32(sm);

    const int tid  = threadIdx.x;
    const int wid  = tid >> 5;
    const int lane = tid & 31;
    const int mw   = wid & 3;   // warp m block (32 rows)
    const int nw   = wid >> 2;  // warp n block (64 cols)
    const int row0 = blockIdx.y * 128;
    const int col0 = blockIdx.x * 128;

    if (tid < 128) sbias[tid] = bias[col0 + tid];

    float acc[2][8][4];
    #pragma unroll
    for (int i = 0; i < 2; i++)
        #pragma unroll
        for (int j = 0; j < 8; j++)
            #pragma unroll
            for (int q = 0; q < 4; q++) acc[i][j][q] = 0.f;

    // staging: 512 (row, seg) pairs, 2 per thread
    const int sr0 = tid >> 2;          // 0..63
    const int ssg = tid & 3;           // 16B granule

    // ldmatrix lane addressing
    const int lr = lane & 15;
    const int lc = lane >> 4;

    for (int kc = 0; kc < K; kc += 32) {
        __syncthreads();
        #pragma unroll
        for (int it = 0; it < 2; it++) {
            int r = sr0 + it * 64;
            uint32_t so = (uint32_t)(r * ASTR + ssg * 16);
            size_t ga = (size_t)(row0 + r) * K + kc + ssg * 8;
            size_t gb = (size_t)(col0 + r) * K + kc + ssg * 8;
            *(uint4*)(sm + SM_AHI + so) = *(const uint4*)(Ahi + ga);
            *(uint4*)(sm + SM_ALO + so) = *(const uint4*)(Alo + ga);
            *(uint4*)(sm + SM_BHI + so) = *(const uint4*)(Bhi + gb);
            *(uint4*)(sm + SM_BLO + so) = *(const uint4*)(Blo + gb);
        }
        __syncthreads();

        #pragma unroll
        for (int ks = 0; ks < 2; ks++) {
            const uint32_t kb = (uint32_t)(lc * 16 + ks * 32);

            uint32_t a_hi[2][4], a_lo[2][4];
            #pragma unroll
            for (int mf = 0; mf < 2; mf++) {
                uint32_t ao = smb + (uint32_t)((mw * 32 + mf * 16 + lr) * ASTR) + kb;
                LDSM_X4(a_hi[mf][0], a_hi[mf][1], a_hi[mf][2], a_hi[mf][3], ao + SM_AHI);
                LDSM_X4(a_lo[mf][0], a_lo[mf][1], a_lo[mf][2], a_lo[mf][3], ao + SM_ALO);
            }

            #pragma unroll
            for (int np = 0; np < 4; np++) {
                uint32_t bo = smb + (uint32_t)((nw * 64 + np * 16 + lr) * ASTR) + kb;
                uint32_t bh0, bh1, bh2, bh3, bl0, bl1, bl2, bl3;
                LDSM_X4(bh0, bh1, bh2, bh3, bo + SM_BHI);
                LDSM_X4(bl0, bl1, bl2, bl3, bo + SM_BLO);
                #pragma unroll
                for (int mf = 0; mf < 2; mf++) {
                    mma16816(acc[mf][np * 2 + 0], a_hi[mf], bh0, bh2);
                    mma16816(acc[mf][np * 2 + 0], a_hi[mf], bl0, bl2);
                    mma16816(acc[mf][np * 2 + 0], a_lo[mf], bh0, bh2);
                    mma16816(acc[mf][np * 2 + 1], a_hi[mf], bh1, bh3);
                    mma16816(acc[mf][np * 2 + 1], a_hi[mf], bl1, bl3);
                    mma16816(acc[mf][np * 2 + 1], a_lo[mf], bh1, bh3);
                }
            }
        }
    }

    // epilogue: C frag (c0,c1)=row r, cols 2c..2c+1 ; (c2,c3)=row r+8
    #pragma unroll
    for (int mf = 0; mf < 2; mf++) {
        int r_ = row0 + mw * 32 + mf * 16 + (lane >> 2);
        #pragma unroll
        for (int nf = 0; nf < 8; nf++) {
            int cl = nw * 64 + nf * 8 + (lane & 3) * 2;  // col within tile
            float b0 = sbias[cl], b1 = sbias[cl + 1];
            float2 v0 = {acc[mf][nf][0] + b0, acc[mf][nf][1] + b1};
            float2 v1 = {acc[mf][nf][2] + b0, acc[mf][nf][3] + b1};
            *(float2*)(Cout + (size_t)r_ * N + col0 + cl) = v0;
            *(float2*)(Cout + (size_t)(r_ + 8) * N + col0 + cl) = v1;
        }
    }
}

// ---------------------------------------------------------------------------
// Flash attention (causal), fp32 SIMT (unchanged, proven).
// ---------------------------------------------------------------------------
__global__ __launch_bounds__(256)
void attn_kernel(const float* __restrict__ qkv, float* __restrict__ y)
{
    extern __shared__ float smf[];
    float* Qt   = smf;
    float* KV   = Qt + 64 * 64;
    float* Ss   = KV + 64 * 64;
    float* mrow = Ss + 64 * 65;
    float* lrow = mrow + 64;
    float* arow = lrow + 64;

    const int qb = (gridDim.x - 1) - blockIdx.x;
    const int h  = blockIdx.y;
    const int b  = blockIdx.z;
    const int tid = threadIdx.x;
    const int tx  = tid & 15;
    const int ty  = tid >> 4;
    const float scale = 0.125f;
    const int am   = tid >> 2;
    const int ak16 = (tid & 3) << 4;

    {
        const float* qbase = qkv + (size_t)(b * T_ + qb * 64 + am) * (3 * C_) + h * HD_ + ak16;
        #pragma unroll
        for (int i = 0; i < 4; i++) {
            float4 v = *(const float4*)(qbase + i * 4);
            int d = ak16 + i * 4;
            Qt[(d+0)*64 + am] = v.x; Qt[(d+1)*64 + am] = v.y;
            Qt[(d+2)*64 + am] = v.z; Qt[(d+3)*64 + am] = v.w;
        }
    }
    if (tid < 64) { mrow[tid] = -1e30f; lrow[tid] = 0.f; }

    float o[4][4];
    #pragma unroll
    for (int i = 0; i < 4; i++)
        #pragma unroll
        for (int j = 0; j < 4; j++) o[i][j] = 0.f;

    for (int kb = 0; kb <= qb; kb++) {
        __syncthreads();
        {
            const float* kbase = qkv + (size_t)(b * T_ + kb * 64 + am) * (3 * C_) + C_ + h * HD_ + ak16;
            #pragma unroll
            for (int i = 0; i < 4; i++) {
                float4 v = *(const float4*)(kbase + i * 4);
                int d = ak16 + i * 4;
                KV[(d+0)*64 + am] = v.x; KV[(d+1)*64 + am] = v.y;
                KV[(d+2)*64 + am] = v.z; KV[(d+3)*64 + am] = v.w;
            }
        }
        __syncthreads();

        float s[4][4];
        #pragma unroll
        for (int i = 0; i < 4; i++)
            #pragma unroll
            for (int j = 0; j < 4; j++) s[i][j] = 0.f;

        #pragma unroll 8
        for (int kk = 0; kk < 64; kk++) {
            float4 a = *(const float4*)&Qt[kk * 64 + (ty << 2)];
            float4 bb = *(const float4*)&KV[kk * 64 + (tx << 2)];
            float ar[4] = {a.x, a.y, a.z, a.w};
            float br[4] = {bb.x, bb.y, bb.z, bb.w};
            #pragma unroll
            for (int i = 0; i < 4; i++)
                #pragma unroll
                for (int j = 0; j < 4; j++)
                    s[i][j] += ar[i] * br[j];
        }

        #pragma unroll
        for (int i = 0; i < 4; i++) {
            int qrow = qb * 64 + (ty << 2) + i;
            #pragma unroll
            for (int j = 0; j < 4; j++) {
                int kcol = kb * 64 + (tx << 2) + j;
                float val = (kcol > qrow) ? -1e30f : s[i][j] * scale;
                Ss[((ty << 2) + i) * 65 + (tx << 2) + j] = val;
            }
        }
        __syncthreads();

        {
            const float* vbase = qkv + (size_t)(b * T_ + kb * 64 + am) * (3 * C_) + 2 * C_ + h * HD_ + ak16;
            #pragma unroll
            for (int i = 0; i < 4; i++)
                *(float4*)&KV[am * 64 + ak16 + i * 4] = *(const float4*)(vbase + i * 4);
        }

        {
            const int row = tid >> 2;
            const int seg = (tid & 3) << 4;
            float mx = -1e30f;
            #pragma unroll
            for (int c = 0; c < 16; c++)
                mx = fmaxf(mx, Ss[row * 65 + seg + c]);
            mx = fmaxf(mx, __shfl_xor_sync(0xffffffffu, mx, 1));
            mx = fmaxf(mx, __shfl_xor_sync(0xffffffffu, mx, 2));
            float mold = mrow[row];
            float mnew = fmaxf(mold, mx);
            float sum = 0.f;
            #pragma unroll
            for (int c = 0; c < 16; c++) {
                float p = __expf(Ss[row * 65 + seg + c] - mnew);
                Ss[row * 65 + seg + c] = p;
                sum += p;
            }
            sum += __shfl_xor_sync(0xffffffffu, sum, 1);
            sum += __shfl_xor_sync(0xffffffffu, sum, 2);
            if ((tid & 3) == 0) {
                float alpha = __expf(mold - mnew);
                arow[row] = alpha;
                lrow[row] = lrow[row] * alpha + sum;
                mrow[row] = mnew;
            }
        }
        __syncthreads();

        float al[4];
        #pragma unroll
        for (int i = 0; i < 4; i++) al[i] = arow[(ty << 2) + i];
        #pragma unroll
        for (int i = 0; i < 4; i++)
            #pragma unroll
            for (int j = 0; j < 4; j++) o[i][j] *= al[i];

        #pragma unroll 8
        for (int kk = 0; kk < 64; kk++) {
            float p[4];
            #pragma unroll
            for (int i = 0; i < 4; i++)
                p[i] = Ss[((ty << 2) + i) * 65 + kk];
            float4 vv = *(const float4*)&KV[kk * 64 + (tx << 2)];
            float vr[4] = {vv.x, vv.y, vv.z, vv.w};
            #pragma unroll
            for (int i = 0; i < 4; i++)
                #pragma unroll
                for (int j = 0; j < 4; j++)
                    o[i][j] += p[i] * vr[j];
        }
    }

    #pragma unroll
    for (int i = 0; i < 4; i++) {
        float linv = 1.f / lrow[(ty << 2) + i];
        float4 ov;
        ov.x = o[i][0] * linv; ov.y = o[i][1] * linv;
        ov.z = o[i][2] * linv; ov.w = o[i][3] * linv;
        int q = qb * 64 + (ty << 2) + i;
        *(float4*)(y + (size_t)(b * T_ + q) * C_ + h * HD_ + (tx << 2)) = ov;
    }
}

// ---------------------------------------------------------------------------
extern "C" void kernel_launch(void* const* d_in, const int* in_sizes, int n_in,
                              void* d_out, int out_size)
{
    const float* x      = (const float*)d_in[0];
    const float* W_attn = (const float*)d_in[1];
    const float* b_attn = (const float*)d_in[2];
    const float* W_proj = (const float*)d_in[3];
    const float* b_proj = (const float*)d_in[4];
    float* out = (float*)d_out;

    float *qkv_ptr, *y_ptr;
    __nv_bfloat16 *xhi, *xlo, *wthi, *wtlo, *wpthi, *wptlo, *yhi, *ylo;
    cudaGetSymbolAddress((void**)&qkv_ptr, g_qkv);
    cudaGetSymbolAddress((void**)&y_ptr,   g_y);
    cudaGetSymbolAddress((void**)&xhi,  g_xhi);
    cudaGetSymbolAddress((void**)&xlo,  g_xlo);
    cudaGetSymbolAddress((void**)&wthi, g_wthi);
    cudaGetSymbolAddress((void**)&wtlo, g_wtlo);
    cudaGetSymbolAddress((void**)&wpthi, g_wpthi);
    cudaGetSymbolAddress((void**)&wptlo, g_wptlo);
    cudaGetSymbolAddress((void**)&yhi,  g_yhi);
    cudaGetSymbolAddress((void**)&ylo,  g_ylo);

    const int ATTN_SMEM = (64*64 + 64*64 + 64*65 + 3*64) * (int)sizeof(float);
    cudaFuncSetAttribute(attn_kernel,
                         cudaFuncAttributeMaxDynamicSharedMemorySize, ATTN_SMEM);

    // 1) conversions
    convert_hilo<<<(M_ * C_) / 1024, 256>>>(x, xhi, xlo, M_ * C_);
    transpose_convert<<<dim3(3 * C_ / 32, C_ / 32), 256>>>(W_attn, wthi, wtlo, C_, 3 * C_);
    transpose_convert<<<dim3(C_ / 32, C_ / 32), 256>>>(W_proj, wpthi, wptlo, C_, C_);

    // 2) qkv = x @ W_attn + b_attn   (HMMA bf16 hi/lo)
    gemm_mma_kernel<<<dim3(3 * C_ / 128, M_ / 128), 256>>>(
        xhi, xlo, wthi, wtlo, b_attn, qkv_ptr, M_, 3 * C_, C_);

    // 3) flash attention -> y
    attn_kernel<<<dim3(T_ / 64, NH_, B_), 256, ATTN_SMEM>>>(qkv_ptr, y_ptr);

    // 4) y -> hi/lo
    convert_hilo<<<(M_ * C_) / 1024, 256>>>(y_ptr, yhi, ylo, M_ * C_);

    // 5) out = y @ W_proj + b_proj   (HMMA bf16 hi/lo)
    gemm_mma_kernel<<<dim3(C_ / 128, M_ / 128), 256>>>(
        yhi, ylo, wpthi, wptlo, b_proj, out, M_, C_, C_);
}

// round 4
// speedup vs baseline: 4.1372x; 1.6323x over previous
#include <cuda_runtime.h>
#include <cuda_bf16.h>
#include <cstdint>
#include <math.h>

#define B_  4
#define T_  2048
#define C_  1024
#define NH_ 16
#define HD_ 64
#define M_  (B_*T_)          // 8192 tokens

// ---------------- scratch (static device globals; no runtime alloc) --------
__device__ __align__(256) float          g_qkv [(size_t)M_ * 3 * C_];
__device__ __align__(256) __nv_bfloat16  g_xhi [(size_t)M_ * C_];
__device__ __align__(256) __nv_bfloat16  g_xlo [(size_t)M_ * C_];
__device__ __align__(256) __nv_bfloat16  g_wthi[(size_t)3 * C_ * C_];  // W_attn^T [3C, C]
__device__ __align__(256) __nv_bfloat16  g_wtlo[(size_t)3 * C_ * C_];
__device__ __align__(256) __nv_bfloat16  g_wpthi[(size_t)C_ * C_];     // W_proj^T [C, C]
__device__ __align__(256) __nv_bfloat16  g_wptlo[(size_t)C_ * C_];
__device__ __align__(256) __nv_bfloat16  g_yhi [(size_t)M_ * C_];
__device__ __align__(256) __nv_bfloat16  g_ylo [(size_t)M_ * C_];

// ---------------- helpers ---------------------------------------------------
__device__ __forceinline__ uint32_t smem_u32(const void* p) {
    uint32_t a;
    asm("{ .reg .u64 t; cvta.to.shared.u64 t, %1; cvt.u32.u64 %0, t; }" : "=r"(a) : "l"(p));
    return a;
}

#define LDSM_X4(r0, r1, r2, r3, addr) \
    asm volatile("ldmatrix.sync.aligned.m8n8.x4.shared.b16 {%0,%1,%2,%3}, [%4];" \
        : "=r"(r0), "=r"(r1), "=r"(r2), "=r"(r3) : "r"(addr))

__device__ __forceinline__ void mma16816(float* d, const uint32_t* a,
                                         uint32_t b0, uint32_t b1) {
    asm volatile(
        "mma.sync.aligned.m16n8k16.row.col.f32.bf16.bf16.f32 "
        "{%0,%1,%2,%3}, {%4,%5,%6,%7}, {%8,%9}, {%0,%1,%2,%3};"
        : "+f"(d[0]), "+f"(d[1]), "+f"(d[2]), "+f"(d[3])
        : "r"(a[0]), "r"(a[1]), "r"(a[2]), "r"(a[3]), "r"(b0), "r"(b1));
}

// pack (a,b) into bf16x2 hi word-pair + residual lo word-pair (lo16 = a)
__device__ __forceinline__ void pack_hilo(float a, float b, uint32_t& h, uint32_t& l) {
    asm("cvt.rn.bf16x2.f32 %0, %1, %2;" : "=r"(h) : "f"(b), "f"(a));
    float fa = __uint_as_float(h << 16);
    float fb = __uint_as_float(h & 0xffff0000u);
    asm("cvt.rn.bf16x2.f32 %0, %1, %2;" : "=r"(l) : "f"(b - fb), "f"(a - fa));
}

__device__ __forceinline__ float ex2f(float x) {
    float r; asm("ex2.approx.f32 %0, %1;" : "=f"(r) : "f"(x)); return r;
}

// ---------------- conversion kernels ----------------------------------------
__global__ __launch_bounds__(256)
void convert_hilo(const float* __restrict__ in, __nv_bfloat16* __restrict__ hi,
                  __nv_bfloat16* __restrict__ lo, int n)
{
    int i = (blockIdx.x * 256 + threadIdx.x) * 4;
    if (i >= n) return;
    float4 v = *(const float4*)(in + i);
    uint32_t h0, l0, h1, l1;
    pack_hilo(v.x, v.y, h0, l0);
    pack_hilo(v.z, v.w, h1, l1);
    *(uint2*)(hi + i) = make_uint2(h0, h1);
    *(uint2*)(lo + i) = make_uint2(l0, l1);
}

// W [K,N] fp32 -> Wt hi/lo [N,K] bf16 (transpose + split)
__global__ __launch_bounds__(256)
void transpose_convert(const float* __restrict__ W, __nv_bfloat16* __restrict__ Thi,
                       __nv_bfloat16* __restrict__ Tlo, int K, int N)
{
    __shared__ float t[32][33];
    int n0 = blockIdx.x * 32, k0 = blockIdx.y * 32;
    int tx = threadIdx.x & 31, ty = threadIdx.x >> 5;  // 32x8
    #pragma unroll
    for (int i = 0; i < 32; i += 8)
        t[ty + i][tx] = W[(size_t)(k0 + ty + i) * N + n0 + tx];
    __syncthreads();
    #pragma unroll
    for (int i = 0; i < 32; i += 8) {
        float v = t[tx][ty + i];
        size_t o = (size_t)(n0 + ty + i) * K + k0 + tx;
        __nv_bfloat16 h = __float2bfloat16_rn(v);
        Thi[o] = h;
        Tlo[o] = __float2bfloat16_rn(v - __bfloat162float(h));
    }
}

// ---------------- mma.sync GEMM: C[M,N] = A[M,K] @ B[N,K]^T + bias ----------
#define ASTR 80
#define SM_AHI 0
#define SM_ALO 10240
#define SM_BHI 20480
#define SM_BLO 30720
#define SM_BIAS 40960

__global__ __launch_bounds__(256)
void gemm_mma_kernel(const __nv_bfloat16* __restrict__ Ahi, const __nv_bfloat16* __restrict__ Alo,
                     const __nv_bfloat16* __restrict__ Bhi, const __nv_bfloat16* __restrict__ Blo,
                     const float* __restrict__ bias, float* __restrict__ Cout,
                     int M, int N, int K)
{
    __shared__ __align__(16) char sm[41472];
    float* sbias = (float*)(sm + SM_BIAS);
    const uint32_t smb = smem_u32(sm);

    const int tid  = threadIdx.x;
    const int wid  = tid >> 5;
    const int lane = tid & 31;
    const int mw   = wid & 3;
    const int nw   = wid >> 2;
    const int row0 = blockIdx.y * 128;
    const int col0 = blockIdx.x * 128;

    if (tid < 128) sbias[tid] = bias[col0 + tid];

    float acc[2][8][4];
    #pragma unroll
    for (int i = 0; i < 2; i++)
        #pragma unroll
        for (int j = 0; j < 8; j++)
            #pragma unroll
            for (int q = 0; q < 4; q++) acc[i][j][q] = 0.f;

    const int sr0 = tid >> 2;
    const int ssg = tid & 3;
    const int lr = lane & 15;
    const int lc = lane >> 4;

    for (int kc = 0; kc < K; kc += 32) {
        __syncthreads();
        #pragma unroll
        for (int it = 0; it < 2; it++) {
            int r = sr0 + it * 64;
            uint32_t so = (uint32_t)(r * ASTR + ssg * 16);
            size_t ga = (size_t)(row0 + r) * K + kc + ssg * 8;
            size_t gb = (size_t)(col0 + r) * K + kc + ssg * 8;
            *(uint4*)(sm + SM_AHI + so) = *(const uint4*)(Ahi + ga);
            *(uint4*)(sm + SM_ALO + so) = *(const uint4*)(Alo + ga);
            *(uint4*)(sm + SM_BHI + so) = *(const uint4*)(Bhi + gb);
            *(uint4*)(sm + SM_BLO + so) = *(const uint4*)(Blo + gb);
        }
        __syncthreads();

        #pragma unroll
        for (int ks = 0; ks < 2; ks++) {
            const uint32_t kb = (uint32_t)(lc * 16 + ks * 32);

            uint32_t a_hi[2][4], a_lo[2][4];
            #pragma unroll
            for (int mf = 0; mf < 2; mf++) {
                uint32_t ao = smb + (uint32_t)((mw * 32 + mf * 16 + lr) * ASTR) + kb;
                LDSM_X4(a_hi[mf][0], a_hi[mf][1], a_hi[mf][2], a_hi[mf][3], ao + SM_AHI);
                LDSM_X4(a_lo[mf][0], a_lo[mf][1], a_lo[mf][2], a_lo[mf][3], ao + SM_ALO);
            }

            #pragma unroll
            for (int np = 0; np < 4; np++) {
                uint32_t bo = smb + (uint32_t)((nw * 64 + np * 16 + lr) * ASTR) + kb;
                uint32_t bh0, bh1, bh2, bh3, bl0, bl1, bl2, bl3;
                LDSM_X4(bh0, bh1, bh2, bh3, bo + SM_BHI);
                LDSM_X4(bl0, bl1, bl2, bl3, bo + SM_BLO);
                #pragma unroll
                for (int mf = 0; mf < 2; mf++) {
                    mma16816(acc[mf][np * 2 + 0], a_hi[mf], bh0, bh2);
                    mma16816(acc[mf][np * 2 + 0], a_hi[mf], bl0, bl2);
                    mma16816(acc[mf][np * 2 + 0], a_lo[mf], bh0, bh2);
                    mma16816(acc[mf][np * 2 + 1], a_hi[mf], bh1, bh3);
                    mma16816(acc[mf][np * 2 + 1], a_hi[mf], bl1, bl3);
                    mma16816(acc[mf][np * 2 + 1], a_lo[mf], bh1, bh3);
                }
            }
        }
    }

    #pragma unroll
    for (int mf = 0; mf < 2; mf++) {
        int r_ = row0 + mw * 32 + mf * 16 + (lane >> 2);
        #pragma unroll
        for (int nf = 0; nf < 8; nf++) {
            int cl = nw * 64 + nf * 8 + (lane & 3) * 2;
            float b0 = sbias[cl], b1 = sbias[cl + 1];
            float2 v0 = {acc[mf][nf][0] + b0, acc[mf][nf][1] + b1};
            float2 v1 = {acc[mf][nf][2] + b0, acc[mf][nf][3] + b1};
            *(float2*)(Cout + (size_t)r_ * N + col0 + cl) = v0;
            *(float2*)(Cout + (size_t)(r_ + 8) * N + col0 + cl) = v1;
        }
    }
}

// ---------------- tensor-core flash attention --------------------------------
// CTA: 128 q-rows x (head, batch). 8 warps, each owns 16 q-rows.
// BK=64. K/V converted fp32->bf16 hi/lo into SMEM per tile; V transposed.
// S and P in register fragments; softmax in log2 domain; hi/lo 3-term MMAs.
#define AT_STR 144
#define A_QHI 0
#define A_QLO 18432
#define A_KHI 36864
#define A_KLO 46080
#define A_VHI 55296
#define A_VLO 64512
#define ATTN_SMEM 73728

__global__ __launch_bounds__(256)
void attn_mma_kernel(const float* __restrict__ qkv,
                     __nv_bfloat16* __restrict__ yhi, __nv_bfloat16* __restrict__ ylo)
{
    extern __shared__ char sm[];
    const uint32_t smb = smem_u32(sm);
    const int tid = threadIdx.x, lane = tid & 31, wid = tid >> 5;
    const int qb = (int)(gridDim.x - 1 - blockIdx.x);  // heavy first
    const int h  = blockIdx.y, b = blockIdx.z;
    const float cs = 0.125f * 1.44269504089f;  // scale * log2(e)

    // ---- load Q tile (128 x 64) as hi/lo bf16 ----
    {
        const int r = tid >> 2, dseg = (tid & 3) << 4;
        #pragma unroll
        for (int it = 0; it < 2; it++) {
            int row = it * 64 + r;
            const float* qg = qkv + (size_t)(b * T_ + qb * 128 + row) * (3 * C_) + h * HD_ + dseg;
            char* dhi = sm + A_QHI + row * AT_STR + dseg * 2;
            char* dlo = sm + A_QLO + row * AT_STR + dseg * 2;
            #pragma unroll
            for (int i = 0; i < 4; i++) {
                float4 v = *(const float4*)(qg + i * 4);
                uint32_t h0, l0, h1, l1;
                pack_hilo(v.x, v.y, h0, l0);
                pack_hilo(v.z, v.w, h1, l1);
                *(uint2*)(dhi + i * 8) = make_uint2(h0, h1);
                *(uint2*)(dlo + i * 8) = make_uint2(l0, l1);
            }
        }
    }

    float m0 = -1e30f, m1 = -1e30f, lsum0 = 0.f, lsum1 = 0.f;
    float o[8][4];
    #pragma unroll
    for (int j = 0; j < 8; j++)
        #pragma unroll
        for (int q = 0; q < 4; q++) o[j][q] = 0.f;

    const int lr = lane & 15, lc = lane >> 4;
    const int rowg0 = qb * 128 + wid * 16 + (lane >> 2);
    const int ntiles = 2 * qb + 2;

    for (int kt = 0; kt < ntiles; kt++) {
        __syncthreads();
        // ---- K tile (64 keys x 64 d) hi/lo ----
        {
            const int key = tid >> 2, dseg = (tid & 3) << 4;
            const float* kg = qkv + (size_t)(b * T_ + kt * 64 + key) * (3 * C_) + C_ + h * HD_ + dseg;
            char* dhi = sm + A_KHI + key * AT_STR + dseg * 2;
            char* dlo = sm + A_KLO + key * AT_STR + dseg * 2;
            #pragma unroll
            for (int i = 0; i < 4; i++) {
                float4 v = *(const float4*)(kg + i * 4);
                uint32_t h0, l0, h1, l1;
                pack_hilo(v.x, v.y, h0, l0);
                pack_hilo(v.z, v.w, h1, l1);
                *(uint2*)(dhi + i * 8) = make_uint2(h0, h1);
                *(uint2*)(dlo + i * 8) = make_uint2(l0, l1);
            }
        }
        // ---- V tile transposed: Vt[d][key] hi/lo ----
        {
            const int vkey = tid & 63, dbase = (tid >> 6) << 4;
            const float* vg = qkv + (size_t)(b * T_ + kt * 64 + vkey) * (3 * C_) + 2 * C_ + h * HD_ + dbase;
            #pragma unroll
            for (int i = 0; i < 4; i++) {
                float4 v = *(const float4*)(vg + i * 4);
                float vv[4] = {v.x, v.y, v.z, v.w};
                #pragma unroll
                for (int e = 0; e < 4; e++) {
                    int d = dbase + i * 4 + e;
                    __nv_bfloat16 hv = __float2bfloat16_rn(vv[e]);
                    *(__nv_bfloat16*)(sm + A_VHI + d * AT_STR + vkey * 2) = hv;
                    *(__nv_bfloat16*)(sm + A_VLO + d * AT_STR + vkey * 2) =
                        __float2bfloat16_rn(vv[e] - __bfloat162float(hv));
                }
            }
        }
        __syncthreads();

        // ---- S = Q K^T (warp: 16 rows x 64 keys) ----
        float s[8][4];
        #pragma unroll
        for (int j = 0; j < 8; j++)
            #pragma unroll
            for (int q = 0; q < 4; q++) s[j][q] = 0.f;

        #pragma unroll
        for (int ks = 0; ks < 4; ks++) {
            const uint32_t kb = (uint32_t)(lc * 16 + ks * 32);
            uint32_t ahi[4], alo[4];
            uint32_t ao = smb + (uint32_t)((wid * 16 + lr) * AT_STR) + kb;
            LDSM_X4(ahi[0], ahi[1], ahi[2], ahi[3], ao + A_QHI);
            LDSM_X4(alo[0], alo[1], alo[2], alo[3], ao + A_QLO);
            #pragma unroll
            for (int np = 0; np < 4; np++) {
                uint32_t bo = smb + (uint32_t)((np * 16 + lr) * AT_STR) + kb;
                uint32_t bh0, bh1, bh2, bh3, bl0, bl1, bl2, bl3;
                LDSM_X4(bh0, bh1, bh2, bh3, bo + A_KHI);
                LDSM_X4(bl0, bl1, bl2, bl3, bo + A_KLO);
                mma16816(s[np * 2 + 0], ahi, bh0, bh2);
                mma16816(s[np * 2 + 0], ahi, bl0, bl2);
                mma16816(s[np * 2 + 0], alo, bh0, bh2);
                mma16816(s[np * 2 + 1], ahi, bh1, bh3);
                mma16816(s[np * 2 + 1], ahi, bl1, bl3);
                mma16816(s[np * 2 + 1], alo, bh1, bh3);
            }
        }

        // ---- scale to log2 domain + causal mask ----
        #pragma unroll
        for (int j = 0; j < 8; j++)
            #pragma unroll
            for (int q = 0; q < 4; q++) s[j][q] *= cs;

        if (kt >= 2 * qb) {   // only last two tiles touch the diagonal
            const int colb = kt * 64 + 2 * (lane & 3);
            #pragma unroll
            for (int j = 0; j < 8; j++) {
                int c0 = colb + 8 * j;
                if (c0     > rowg0)     s[j][0] = -1e30f;
                if (c0 + 1 > rowg0)     s[j][1] = -1e30f;
                if (c0     > rowg0 + 8) s[j][2] = -1e30f;
                if (c0 + 1 > rowg0 + 8) s[j][3] = -1e30f;
            }
        }

        // ---- online softmax (rows owned by quad) ----
        float mx0 = -1e30f, mx1 = -1e30f;
        #pragma unroll
        for (int j = 0; j < 8; j++) {
            mx0 = fmaxf(mx0, fmaxf(s[j][0], s[j][1]));
            mx1 = fmaxf(mx1, fmaxf(s[j][2], s[j][3]));
        }
        mx0 = fmaxf(mx0, __shfl_xor_sync(0xffffffffu, mx0, 1));
        mx0 = fmaxf(mx0, __shfl_xor_sync(0xffffffffu, mx0, 2));
        mx1 = fmaxf(mx1, __shfl_xor_sync(0xffffffffu, mx1, 1));
        mx1 = fmaxf(mx1, __shfl_xor_sync(0xffffffffu, mx1, 2));

        float mn0 = fmaxf(m0, mx0), mn1 = fmaxf(m1, mx1);
        float a0 = ex2f(m0 - mn0),  a1 = ex2f(m1 - mn1);
        m0 = mn0; m1 = mn1;

        float sum0 = 0.f, sum1 = 0.f;
        #pragma unroll
        for (int j = 0; j < 8; j++) {
            s[j][0] = ex2f(s[j][0] - mn0);
            s[j][1] = ex2f(s[j][1] - mn0);
            s[j][2] = ex2f(s[j][2] - mn1);
            s[j][3] = ex2f(s[j][3] - mn1);
            sum0 += s[j][0] + s[j][1];
            sum1 += s[j][2] + s[j][3];
        }
        sum0 += __shfl_xor_sync(0xffffffffu, sum0, 1);
        sum0 += __shfl_xor_sync(0xffffffffu, sum0, 2);
        sum1 += __shfl_xor_sync(0xffffffffu, sum1, 1);
        sum1 += __shfl_xor_sync(0xffffffffu, sum1, 2);
        lsum0 = lsum0 * a0 + sum0;
        lsum1 = lsum1 * a1 + sum1;

        #pragma unroll
        for (int j = 0; j < 8; j++) {
            o[j][0] *= a0; o[j][1] *= a0;
            o[j][2] *= a1; o[j][3] *= a1;
        }

        // ---- P fragments (C layout == A layout), hi/lo split ----
        uint32_t phi[4][4], plo[4][4];
        #pragma unroll
        for (int s2 = 0; s2 < 4; s2++) {
            pack_hilo(s[2*s2  ][0], s[2*s2  ][1], phi[s2][0], plo[s2][0]);
            pack_hilo(s[2*s2  ][2], s[2*s2  ][3], phi[s2][1], plo[s2][1]);
            pack_hilo(s[2*s2+1][0], s[2*s2+1][1], phi[s2][2], plo[s2][2]);
            pack_hilo(s[2*s2+1][2], s[2*s2+1][3], phi[s2][3], plo[s2][3]);
        }

        // ---- O += P @ V ----
        #pragma unroll
        for (int s2 = 0; s2 < 4; s2++) {
            const uint32_t kb = (uint32_t)(lc * 16 + s2 * 32);
            #pragma unroll
            for (int np = 0; np < 4; np++) {
                uint32_t bo = smb + (uint32_t)((np * 16 + lr) * AT_STR) + kb;
                uint32_t bh0, bh1, bh2, bh3, bl0, bl1, bl2, bl3;
                LDSM_X4(bh0, bh1, bh2, bh3, bo + A_VHI);
                LDSM_X4(bl0, bl1, bl2, bl3, bo + A_VLO);
                mma16816(o[np * 2 + 0], phi[s2], bh0, bh2);
                mma16816(o[np * 2 + 0], phi[s2], bl0, bl2);
                mma16816(o[np * 2 + 0], plo[s2], bh0, bh2);
                mma16816(o[np * 2 + 1], phi[s2], bh1, bh3);
                mma16816(o[np * 2 + 1], phi[s2], bl1, bl3);
                mma16816(o[np * 2 + 1], plo[s2], bh1, bh3);
            }
        }
    }

    // ---- epilogue: O/l -> yhi/ylo bf16 ----
    float inv0 = 1.f / lsum0, inv1 = 1.f / lsum1;
    const int tok0 = b * T_ + qb * 128 + wid * 16 + (lane >> 2);
    #pragma unroll
    for (int nf = 0; nf < 8; nf++) {
        int d = h * HD_ + nf * 8 + (lane & 3) * 2;
        uint32_t hh, ll;
        pack_hilo(o[nf][0] * inv0, o[nf][1] * inv0, hh, ll);
        *(uint32_t*)(yhi + (size_t)tok0 * C_ + d) = hh;
        *(uint32_t*)(ylo + (size_t)tok0 * C_ + d) = ll;
        pack_hilo(o[nf][2] * inv1, o[nf][3] * inv1, hh, ll);
        *(uint32_t*)(yhi + (size_t)(tok0 + 8) * C_ + d) = hh;
        *(uint32_t*)(ylo + (size_t)(tok0 + 8) * C_ + d) = ll;
    }
}

// ---------------------------------------------------------------------------
extern "C" void kernel_launch(void* const* d_in, const int* in_sizes, int n_in,
                              void* d_out, int out_size)
{
    const float* x      = (const float*)d_in[0];
    const float* W_attn = (const float*)d_in[1];
    const float* b_attn = (const float*)d_in[2];
    const float* W_proj = (const float*)d_in[3];
    const float* b_proj = (const float*)d_in[4];
    float* out = (float*)d_out;

    float* qkv_ptr;
    __nv_bfloat16 *xhi, *xlo, *wthi, *wtlo, *wpthi, *wptlo, *yhi, *ylo;
    cudaGetSymbolAddress((void**)&qkv_ptr, g_qkv);
    cudaGetSymbolAddress((void**)&xhi,  g_xhi);
    cudaGetSymbolAddress((void**)&xlo,  g_xlo);
    cudaGetSymbolAddress((void**)&wthi, g_wthi);
    cudaGetSymbolAddress((void**)&wtlo, g_wtlo);
    cudaGetSymbolAddress((void**)&wpthi, g_wpthi);
    cudaGetSymbolAddress((void**)&wptlo, g_wptlo);
    cudaGetSymbolAddress((void**)&yhi,  g_yhi);
    cudaGetSymbolAddress((void**)&ylo,  g_ylo);

    cudaFuncSetAttribute(attn_mma_kernel,
                         cudaFuncAttributeMaxDynamicSharedMemorySize, ATTN_SMEM);

    // 1) conversions
    convert_hilo<<<(M_ * C_) / 1024, 256>>>(x, xhi, xlo, M_ * C_);
    transpose_convert<<<dim3(3 * C_ / 32, C_ / 32), 256>>>(W_attn, wthi, wtlo, C_, 3 * C_);
    transpose_convert<<<dim3(C_ / 32, C_ / 32), 256>>>(W_proj, wpthi, wptlo, C_, C_);

    // 2) qkv = x @ W_attn + b_attn   (HMMA bf16 hi/lo)
    gemm_mma_kernel<<<dim3(3 * C_ / 128, M_ / 128), 256>>>(
        xhi, xlo, wthi, wtlo, b_attn, qkv_ptr, M_, 3 * C_, C_);

    // 3) tensor-core flash attention -> yhi/ylo (bf16 hi/lo direct)
    attn_mma_kernel<<<dim3(T_ / 128, NH_, B_), 256, ATTN_SMEM>>>(qkv_ptr, yhi, ylo);

    // 4) out = y @ W_proj + b_proj   (HMMA bf16 hi/lo)
    gemm_mma_kernel<<<dim3(C_ / 128, M_ / 128), 256>>>(
        yhi, ylo, wpthi, wptlo, b_proj, out, M_, C_, C_);
}